// round 14
// baseline (speedup 1.0000x reference)
#include <cuda_runtime.h>
#include <cuda_bf16.h>
#include <math.h>
#include <stdint.h>

#define Bc   2
#define Sc   2048
#define HIDc 1024
#define NHc  16
#define HDc  64
#define BSc  (Bc * Sc)
#define BHc  (Bc * NHc)

#define LDg 24    // smem bf16 row stride for BK=16 tiles
#define LDs 72    // smem bf16 row stride for scores Q/K staging
#define LDsim 136 // smem float row stride for sim tile (8 mod 32 -> conflict-free f2 reads)

// Scratch (device globals — no allocation allowed)
__device__ float g_Q[(size_t)BHc * Sc * HDc];    // [bh][s][d]
__device__ float g_K[(size_t)BHc * Sc * HDc];    // [bh][s][d]
__device__ float g_V[(size_t)BHc * Sc * HDc];    // [bh][d][s]  (transposed)
__device__ float g_O[(size_t)Bc  * Sc * HIDc];   // [b][s][hid]
__device__ float g_part[(size_t)BHc * Sc * 16];  // per-row per-ntile partial exp sums
__device__ float g_inv [(size_t)BHc * Sc];       // 1 / rowsum(exp)

// ---------------------------------------------------------------------------
// helpers
// ---------------------------------------------------------------------------
__device__ __forceinline__ uint32_t ld32bf(const __nv_bfloat16* p) {
    return *reinterpret_cast<const uint32_t*>(p);
}
__device__ __forceinline__ uint32_t pack_bf16x2(float x0, float x1) {
    uint32_t r;
    asm("cvt.rn.bf16x2.f32 %0, %1, %2;" : "=r"(r) : "f"(x1), "f"(x0));
    return r;
}
__device__ __forceinline__ void mma_bf16(float c[4], const uint32_t a[4], const uint32_t b[2]) {
    asm volatile(
        "mma.sync.aligned.m16n8k16.row.col.f32.bf16.bf16.f32 "
        "{%0,%1,%2,%3},{%4,%5,%6,%7},{%8,%9},{%0,%1,%2,%3};"
        : "+f"(c[0]), "+f"(c[1]), "+f"(c[2]), "+f"(c[3])
        : "r"(a[0]), "r"(a[1]), "r"(a[2]), "r"(a[3]), "r"(b[0]), "r"(b[1]));
}
__device__ __forceinline__ void cp_async16(void* smem_ptr, const void* gptr) {
    uint32_t s = (uint32_t)__cvta_generic_to_shared(smem_ptr);
    asm volatile("cp.async.cg.shared.global [%0], [%1], 16;" :: "r"(s), "l"(gptr));
}

// fp32 -> bf16 hi (exact top-16 bits) + bf16 lo (residual)
__device__ __forceinline__ void cvt_store8(const float v[8],
                                           __nv_bfloat16* hi, __nv_bfloat16* lo) {
    uint32_t h[4], l[4];
    #pragma unroll
    for (int i = 0; i < 4; ++i) {
        uint32_t u0 = __float_as_uint(v[2*i]);
        uint32_t u1 = __float_as_uint(v[2*i+1]);
        h[i] = (u0 >> 16) | (u1 & 0xFFFF0000u);
        float l0 = v[2*i]   - __uint_as_float(u0 & 0xFFFF0000u);
        float l1 = v[2*i+1] - __uint_as_float(u1 & 0xFFFF0000u);
        l[i] = pack_bf16x2(l0, l1);
    }
    *reinterpret_cast<uint4*>(hi) = make_uint4(h[0], h[1], h[2], h[3]);
    *reinterpret_cast<uint4*>(lo) = make_uint4(l[0], l[1], l[2], l[3]);
}
__device__ __forceinline__ void cvt_store4(const float v[4],
                                           __nv_bfloat16* hi, __nv_bfloat16* lo) {
    uint32_t h[2], l[2];
    #pragma unroll
    for (int i = 0; i < 2; ++i) {
        uint32_t u0 = __float_as_uint(v[2*i]);
        uint32_t u1 = __float_as_uint(v[2*i+1]);
        h[i] = (u0 >> 16) | (u1 & 0xFFFF0000u);
        float l0 = v[2*i]   - __uint_as_float(u0 & 0xFFFF0000u);
        float l1 = v[2*i+1] - __uint_as_float(u1 & 0xFFFF0000u);
        l[i] = pack_bf16x2(l0, l1);
    }
    *reinterpret_cast<uint2*>(hi) = make_uint2(h[0], h[1]);
    *reinterpret_cast<uint2*>(lo) = make_uint2(l[0], l[1]);
}
__device__ __forceinline__ void cvt_store2(const float v[2],
                                           __nv_bfloat16* hi, __nv_bfloat16* lo) {
    uint32_t u0 = __float_as_uint(v[0]);
    uint32_t u1 = __float_as_uint(v[1]);
    uint32_t h = (u0 >> 16) | (u1 & 0xFFFF0000u);
    float l0 = v[0] - __uint_as_float(u0 & 0xFFFF0000u);
    float l1 = v[1] - __uint_as_float(u1 & 0xFFFF0000u);
    *reinterpret_cast<uint32_t*>(hi) = h;
    *reinterpret_cast<uint32_t*>(lo) = pack_bf16x2(l0, l1);
}
__device__ __forceinline__ void gload8(const float* p, float r[8]) {
    float4 x = *reinterpret_cast<const float4*>(p);
    float4 y = *reinterpret_cast<const float4*>(p + 4);
    r[0]=x.x; r[1]=x.y; r[2]=x.z; r[3]=x.w; r[4]=y.x; r[5]=y.y; r[6]=y.z; r[7]=y.w;
}
__device__ __forceinline__ void gload4(const float* p, float r[4]) {
    float4 x = *reinterpret_cast<const float4*>(p);
    r[0]=x.x; r[1]=x.y; r[2]=x.z; r[3]=x.w;
}

// One BK=16 MMA step for a warp tile (MI x NJ m16n8 tiles), bf16x3 split.
template<int MI, int NJ, int LDm>
__device__ __forceinline__ void mma_tile(
    const __nv_bfloat16* Ah, const __nv_bfloat16* Al,
    const __nv_bfloat16* Bh, const __nv_bfloat16* Bl,
    int aRow0, int bCol0, int g, int t,
    float (&c)[MI][NJ][4])
{
    uint32_t ah[MI][4], al[MI][4], bh[NJ][2], bl[NJ][2];
    #pragma unroll
    for (int mi = 0; mi < MI; ++mi) {
        int r = aRow0 + mi * 16 + g;
        const __nv_bfloat16* p0 = Ah + r * LDm + 2 * t;
        const __nv_bfloat16* p1 = p0 + 8 * LDm;
        ah[mi][0] = ld32bf(p0);     ah[mi][1] = ld32bf(p1);
        ah[mi][2] = ld32bf(p0 + 8); ah[mi][3] = ld32bf(p1 + 8);
        const __nv_bfloat16* q0 = Al + r * LDm + 2 * t;
        const __nv_bfloat16* q1 = q0 + 8 * LDm;
        al[mi][0] = ld32bf(q0);     al[mi][1] = ld32bf(q1);
        al[mi][2] = ld32bf(q0 + 8); al[mi][3] = ld32bf(q1 + 8);
    }
    #pragma unroll
    for (int nj = 0; nj < NJ; ++nj) {
        int n = bCol0 + nj * 8 + g;
        const __nv_bfloat16* p = Bh + n * LDm + 2 * t;
        bh[nj][0] = ld32bf(p); bh[nj][1] = ld32bf(p + 8);
        const __nv_bfloat16* q = Bl + n * LDm + 2 * t;
        bl[nj][0] = ld32bf(q); bl[nj][1] = ld32bf(q + 8);
    }
    #pragma unroll
    for (int mi = 0; mi < MI; ++mi)
        #pragma unroll
        for (int nj = 0; nj < NJ; ++nj) {
            mma_bf16(c[mi][nj], ah[mi], bh[nj]);
            mma_bf16(c[mi][nj], ah[mi], bl[nj]);
            mma_bf16(c[mi][nj], al[mi], bh[nj]);
        }
}

// ---------------------------------------------------------------------------
// GEMM core: 128x128 tile, 512 thr, warp grid 4x4 (warp tile 32x32), dbl buf.
// Epilogue dispatched on runtime `mode`: 0 plain, 1 -> [bh][s][d], 2 -> [bh][d][s]
// ---------------------------------------------------------------------------
__device__ __forceinline__ void gemm_body(
    const float* __restrict__ A, const float* __restrict__ W,
    const float* __restrict__ bias, float* __restrict__ C,
    int N, int K, int mode,
    __nv_bfloat16 (*sA)[2][128 * LDg], __nv_bfloat16 (*sB)[2][128 * LDg])
{
    const int tid = threadIdx.x;
    const int wid = tid >> 5, lane = tid & 31;
    const int wm = wid >> 2, wn = wid & 3;
    const int g = lane >> 2, t = lane & 3;
    const int m0 = blockIdx.y * 128, n0 = blockIdx.x * 128;

    const int lrow = tid >> 2, lcol = (tid & 3) * 4;
    const float* Ap = A + (size_t)(m0 + lrow) * K + lcol;
    const float* Bp = W + (size_t)(n0 + lrow) * K + lcol;

    float c[2][4][4];
    #pragma unroll
    for (int i = 0; i < 2; ++i)
        #pragma unroll
        for (int j = 0; j < 4; ++j)
            #pragma unroll
            for (int k = 0; k < 4; ++k) c[i][j][k] = 0.f;

    float ra[4], rb[4];
    const int KT = K >> 4;

    gload4(Ap, ra);
    gload4(Bp, rb);
    cvt_store4(ra, &sA[0][0][lrow*LDg + lcol], &sA[0][1][lrow*LDg + lcol]);
    cvt_store4(rb, &sB[0][0][lrow*LDg + lcol], &sB[0][1][lrow*LDg + lcol]);
    __syncthreads();

    for (int kt = 0; kt < KT; ++kt) {
        int cur = kt & 1;
        if (kt + 1 < KT) {
            gload4(Ap + (kt + 1) * 16, ra);
            gload4(Bp + (kt + 1) * 16, rb);
        }
        mma_tile<2,4,LDg>(sA[cur][0], sA[cur][1], sB[cur][0], sB[cur][1],
                          wm * 32, wn * 32, g, t, c);
        if (kt + 1 < KT) {
            int nxt = cur ^ 1;
            cvt_store4(ra, &sA[nxt][0][lrow*LDg + lcol], &sA[nxt][1][lrow*LDg + lcol]);
            cvt_store4(rb, &sB[nxt][0][lrow*LDg + lcol], &sB[nxt][1][lrow*LDg + lcol]);
        }
        __syncthreads();
    }

    #pragma unroll
    for (int nj = 0; nj < 4; ++nj) {
        int n = n0 + wn * 32 + nj * 8 + 2 * t;
        float b0 = bias[n], b1 = bias[n + 1];
        #pragma unroll
        for (int mi = 0; mi < 2; ++mi) {
            #pragma unroll
            for (int half = 0; half < 2; ++half) {
                int rr = m0 + wm * 32 + mi * 16 + half * 8 + g;
                float v0 = c[mi][nj][2*half]     + b0;
                float v1 = c[mi][nj][2*half + 1] + b1;
                if (mode == 0) {
                    *reinterpret_cast<float2*>(&C[(size_t)rr * N + n]) = make_float2(v0, v1);
                } else {
                    int b = rr / Sc, s = rr % Sc;
                    int h = n / HDc, d = n % HDc;
                    if (mode == 1) {
                        *reinterpret_cast<float2*>(
                            &C[(((size_t)(b * NHc + h)) * Sc + s) * HDc + d]) = make_float2(v0, v1);
                    } else {
                        C[(((size_t)(b * NHc + h)) * HDc + d)     * Sc + s] = v0;
                        C[(((size_t)(b * NHc + h)) * HDc + d + 1) * Sc + s] = v1;
                    }
                }
            }
        }
    }
}

// Fused Q/K/V projections: blockIdx.z selects the GEMM. 768 CTAs -> 5.2 waves.
__global__ __launch_bounds__(512, 1) void qkv_kernel(
    const float* __restrict__ query, const float* __restrict__ key,
    const float* __restrict__ value,
    const float* __restrict__ Wq, const float* __restrict__ bq,
    const float* __restrict__ Wk, const float* __restrict__ bk,
    const float* __restrict__ Wv, const float* __restrict__ bv,
    float* Qd, float* Kd, float* Vd)
{
    __shared__ __nv_bfloat16 sA[2][2][128 * LDg];
    __shared__ __nv_bfloat16 sB[2][2][128 * LDg];
    const float *A, *W, *bias; float* C; int mode;
    if (blockIdx.z == 0)      { A = query; W = Wq; bias = bq; C = Qd; mode = 1; }
    else if (blockIdx.z == 1) { A = key;   W = Wk; bias = bk; C = Kd; mode = 1; }
    else                      { A = value; W = Wv; bias = bv; C = Vd; mode = 2; }
    gemm_body(A, W, bias, C, HIDc, HIDc, mode, sA, sB);
}

// Output projection
__global__ __launch_bounds__(512, 1) void oproj_kernel(
    const float* __restrict__ A, const float* __restrict__ W,
    const float* __restrict__ bias, float* __restrict__ C)
{
    __shared__ __nv_bfloat16 sA[2][2][128 * LDg];
    __shared__ __nv_bfloat16 sB[2][2][128 * LDg];
    gemm_body(A, W, bias, C, HIDc, HIDc, 0, sA, sB);
}

// ---------------------------------------------------------------------------
// Scores: e = exp(QK/8 + beta*sim, masked) -> weights region + row partials.
// sim tile prefetched via cp.async, overlapped with Q/K staging and MMA.
// ---------------------------------------------------------------------------
__global__ __launch_bounds__(512, 1) void scores_kernel(
    const float* __restrict__ sim, const int* __restrict__ mask,
    const float* __restrict__ beta_p, float* __restrict__ Wt)
{
    extern __shared__ __nv_bfloat16 dsm[];
    __nv_bfloat16* sAh = dsm;
    __nv_bfloat16* sAl = sAh + 128 * LDs;
    __nv_bfloat16* sBh = sAl + 128 * LDs;
    __nv_bfloat16* sBl = sBh + 128 * LDs;
    float* ssim = reinterpret_cast<float*>(sBl + 128 * LDs);  // [128][LDsim]
    __shared__ float spart[128][4];

    const int tid = threadIdx.x;
    const int wid = tid >> 5, lane = tid & 31;
    const int wm = wid >> 2, wn = wid & 3;
    const int g = lane >> 2, t = lane & 3;
    const int bh = blockIdx.z, b = bh >> 4;
    const int m0 = blockIdx.y * 128, n0 = blockIdx.x * 128;

    // --- async prefetch of sim tile: 128 rows x 128 floats ---
    {
        const int r = tid >> 2;
        const int c0 = (tid & 3) * 32;
        const float* gsrc = sim + ((size_t)b * Sc + m0 + r) * Sc + n0 + c0;
        float* sdst = ssim + r * LDsim + c0;
        #pragma unroll
        for (int i = 0; i < 8; ++i)
            cp_async16(sdst + i * 4, gsrc + i * 4);
        asm volatile("cp.async.commit_group;" ::: "memory");
    }

    // --- stage full 128x64 Q and K tiles (hi+lo) ---
    const int lrow = tid >> 2, lcol = (tid & 3) * 16;
    {
        const float* Ap = g_Q + (size_t)bh * Sc * HDc + (size_t)(m0 + lrow) * HDc + lcol;
        const float* Bp = g_K + (size_t)bh * Sc * HDc + (size_t)(n0 + lrow) * HDc + lcol;
        float r0[8], r1[8];
        gload8(Ap, r0); gload8(Ap + 8, r1);
        cvt_store8(r0, &sAh[lrow*LDs + lcol],     &sAl[lrow*LDs + lcol]);
        cvt_store8(r1, &sAh[lrow*LDs + lcol + 8], &sAl[lrow*LDs + lcol + 8]);
        gload8(Bp, r0); gload8(Bp + 8, r1);
        cvt_store8(r0, &sBh[lrow*LDs + lcol],     &sBl[lrow*LDs + lcol]);
        cvt_store8(r1, &sBh[lrow*LDs + lcol + 8], &sBl[lrow*LDs + lcol + 8]);
    }
    __syncthreads();

    float c[2][4][4];
    #pragma unroll
    for (int i = 0; i < 2; ++i)
        #pragma unroll
        for (int j = 0; j < 4; ++j)
            #pragma unroll
            for (int k = 0; k < 4; ++k) c[i][j][k] = 0.f;

    #pragma unroll
    for (int kt = 0; kt < HDc / 16; ++kt) {
        mma_tile<2,4,LDs>(sAh + kt*16, sAl + kt*16, sBh + kt*16, sBl + kt*16,
                          wm * 32, wn * 32, g, t, c);
    }

    asm volatile("cp.async.wait_group 0;" ::: "memory");
    __syncthreads();

    const float beta = *beta_p;
    // hoist mask (8 cols per thread, row-invariant)
    int2 mk[4];
    #pragma unroll
    for (int nj = 0; nj < 4; ++nj)
        mk[nj] = *reinterpret_cast<const int2*>(
            &mask[b * Sc + n0 + wn * 32 + nj * 8 + 2 * t]);

    float rsum[2][2];
    rsum[0][0] = rsum[0][1] = rsum[1][0] = rsum[1][1] = 0.f;

    #pragma unroll
    for (int mi = 0; mi < 2; ++mi) {
        #pragma unroll
        for (int half = 0; half < 2; ++half) {
            int rloc = wm * 32 + mi * 16 + half * 8 + g;
            int qq = m0 + rloc;
            #pragma unroll
            for (int nj = 0; nj < 4; ++nj) {
                int cloc = wn * 32 + nj * 8 + 2 * t;
                float2 sv = *reinterpret_cast<const float2*>(&ssim[rloc * LDsim + cloc]);
                float s0 = c[mi][nj][2*half]     * 0.125f + beta * sv.x;
                float s1 = c[mi][nj][2*half + 1] * 0.125f + beta * sv.y;
                if (mk[nj].x == 0) s0 = -1e30f;
                if (mk[nj].y == 0) s1 = -1e30f;
                float e0 = __expf(s0), e1 = __expf(s1);
                __stcs(reinterpret_cast<float2*>(
                    &Wt[((size_t)bh * Sc + qq) * Sc + n0 + cloc]), make_float2(e0, e1));
                rsum[mi][half] += e0 + e1;
            }
        }
    }
    #pragma unroll
    for (int mi = 0; mi < 2; ++mi)
        #pragma unroll
        for (int half = 0; half < 2; ++half) {
            float v = rsum[mi][half];
            v += __shfl_xor_sync(0xffffffffu, v, 1);
            v += __shfl_xor_sync(0xffffffffu, v, 2);
            if (t == 0) spart[wm * 32 + mi * 16 + half * 8 + g][wn] = v;
        }
    __syncthreads();
    if (tid < 128) {
        float s = spart[tid][0] + spart[tid][1] + spart[tid][2] + spart[tid][3];
        g_part[((size_t)bh * Sc + m0 + tid) * 16 + blockIdx.x] = s;
    }
}

// ---------------------------------------------------------------------------
// inv rowsum
// ---------------------------------------------------------------------------
__global__ __launch_bounds__(256) void inv_kernel()
{
    int i = blockIdx.x * 256 + threadIdx.x;
    const float4* p = reinterpret_cast<const float4*>(g_part + (size_t)i * 16);
    float4 a = p[0], bb = p[1], cc = p[2], d = p[3];
    float s = ((a.x + a.y) + (a.z + a.w)) + ((bb.x + bb.y) + (bb.z + bb.w))
            + ((cc.x + cc.y) + (cc.z + cc.w)) + ((d.x + d.y) + (d.z + d.w));
    g_inv[i] = 1.0f / s;
}

// ---------------------------------------------------------------------------
// AV: normalize e -> p in-place (final attention_weights), O = P @ V^T.
// 128x64 tile, 512 threads, warp grid 4x4 (warp tile 32x16), K=2048 dbl buf.
// grid 512 CTAs (3.5 waves). Streaming loads/stores on the e/p path.
// ---------------------------------------------------------------------------
__global__ __launch_bounds__(512, 1) void av_kernel(float* __restrict__ Wt)
{
    __shared__ __nv_bfloat16 sA[2][2][128 * LDg];
    __shared__ __nv_bfloat16 sB[2][2][64 * LDg];

    const int tid = threadIdx.x;
    const int wid = tid >> 5, lane = tid & 31;
    const int wm = wid >> 2, wn = wid & 3;      // warp tile 32m x 16d
    const int g = lane >> 2, t = lane & 3;
    const int bh = blockIdx.z, b = bh >> 4, h = bh & 15;
    const int m0 = blockIdx.x * 128;

    const int lrowA = tid >> 2, lcolA = (tid & 3) * 4;
    float* ApE = Wt + (size_t)bh * Sc * Sc + (size_t)(m0 + lrowA) * Sc + lcolA;
    const float inv = g_inv[(size_t)bh * Sc + m0 + lrowA];

    const int lrowB = tid >> 3, lcolB = (tid & 7) * 2;
    const float* Bp = g_V + (size_t)bh * HDc * Sc + (size_t)lrowB * Sc + lcolB;

    float c[2][2][4];
    #pragma unroll
    for (int i = 0; i < 2; ++i)
        #pragma unroll
        for (int j = 0; j < 2; ++j)
            #pragma unroll
            for (int k = 0; k < 4; ++k) c[i][j][k] = 0.f;

    float ra[4], rb[2];
    const int KT = Sc / 16;  // 128

    {
        float4 x = __ldcs(reinterpret_cast<const float4*>(ApE));
        x.x*=inv; x.y*=inv; x.z*=inv; x.w*=inv;
        __stcs(reinterpret_cast<float4*>(ApE), x);
        ra[0]=x.x; ra[1]=x.y; ra[2]=x.z; ra[3]=x.w;
        float2 v = *reinterpret_cast<const float2*>(Bp);
        rb[0]=v.x; rb[1]=v.y;
        cvt_store4(ra, &sA[0][0][lrowA*LDg + lcolA], &sA[0][1][lrowA*LDg + lcolA]);
        cvt_store2(rb, &sB[0][0][lrowB*LDg + lcolB], &sB[0][1][lrowB*LDg + lcolB]);
    }
    __syncthreads();

    for (int kt = 0; kt < KT; ++kt) {
        int cur = kt & 1;
        if (kt + 1 < KT) {
            float* pe = ApE + (kt + 1) * 16;
            float4 x = __ldcs(reinterpret_cast<const float4*>(pe));
            x.x*=inv; x.y*=inv; x.z*=inv; x.w*=inv;
            __stcs(reinterpret_cast<float4*>(pe), x);
            ra[0]=x.x; ra[1]=x.y; ra[2]=x.z; ra[3]=x.w;
            float2 v = *reinterpret_cast<const float2*>(Bp + (kt + 1) * 16);
            rb[0]=v.x; rb[1]=v.y;
        }
        mma_tile<2,2,LDg>(sA[cur][0], sA[cur][1], sB[cur][0], sB[cur][1],
                          wm * 32, wn * 16, g, t, c);
        if (kt + 1 < KT) {
            int nxt = cur ^ 1;
            cvt_store4(ra, &sA[nxt][0][lrowA*LDg + lcolA], &sA[nxt][1][lrowA*LDg + lcolA]);
            cvt_store2(rb, &sB[nxt][0][lrowB*LDg + lcolB], &sB[nxt][1][lrowB*LDg + lcolB]);
        }
        __syncthreads();
    }

    #pragma unroll
    for (int mi = 0; mi < 2; ++mi)
        #pragma unroll
        for (int nj = 0; nj < 2; ++nj)
            #pragma unroll
            for (int half = 0; half < 2; ++half) {
                int q = m0 + wm * 32 + mi * 16 + half * 8 + g;
                int d = wn * 16 + nj * 8 + 2 * t;
                float2 vv = make_float2(c[mi][nj][2*half], c[mi][nj][2*half + 1]);
                *reinterpret_cast<float2*>(
                    &g_O[((size_t)(b * Sc) + q) * HIDc + h * HDc + d]) = vv;
            }
}

// ---------------------------------------------------------------------------
extern "C" void kernel_launch(void* const* d_in, const int* in_sizes, int n_in,
                              void* d_out, int out_size)
{
    (void)in_sizes; (void)n_in; (void)out_size;
    const float* query = (const float*)d_in[0];
    const float* key   = (const float*)d_in[1];
    const float* value = (const float*)d_in[2];
    const int*   amask = (const int*)  d_in[3];
    const float* sim   = (const float*)d_in[4];
    const float* Wq    = (const float*)d_in[5];
    const float* bq    = (const float*)d_in[6];
    const float* Wk    = (const float*)d_in[7];
    const float* bk    = (const float*)d_in[8];
    const float* Wv    = (const float*)d_in[9];
    const float* bv    = (const float*)d_in[10];
    const float* Wo    = (const float*)d_in[11];
    const float* bo    = (const float*)d_in[12];
    const float* beta  = (const float*)d_in[13];

    float* out     = (float*)d_out;                      // [B,S,HID]
    float* weights = out + (size_t)Bc * Sc * HIDc;       // [B,NH,S,S]

    const int SCORES_SMEM = 4 * 128 * LDs * 2 + 128 * LDsim * 4;  // 73728+69632

    static float *Qp = nullptr, *Kp = nullptr, *Vp = nullptr, *Op = nullptr;
    if (!Qp) {
        cudaGetSymbolAddress((void**)&Qp, g_Q);
        cudaGetSymbolAddress((void**)&Kp, g_K);
        cudaGetSymbolAddress((void**)&Vp, g_V);
        cudaGetSymbolAddress((void**)&Op, g_O);
        cudaFuncSetAttribute(scores_kernel,
            cudaFuncAttributeMaxDynamicSharedMemorySize, SCORES_SMEM);
    }

    dim3 blk(512);

    dim3 gqkv(HIDc / 128, BSc / 128, 3);   // (8, 32, 3) = 768 CTAs
    qkv_kernel<<<gqkv, blk>>>(query, key, value, Wq, bq, Wk, bk, Wv, bv, Qp, Kp, Vp);

    dim3 gsc(Sc / 128, Sc / 128, BHc);     // (16, 16, 32)
    scores_kernel<<<gsc, blk, SCORES_SMEM>>>(sim, amask, beta, weights);

    inv_kernel<<<(BHc * Sc) / 256, 256>>>();

    dim3 gav(Sc / 128, 1, BHc);            // (16, 1, 32) = 512 CTAs
    av_kernel<<<gav, blk>>>(weights);

    dim3 gop(HIDc / 128, BSc / 128);
    oproj_kernel<<<gop, blk>>>(Op, Wo, bo, out);
}

// round 15
// speedup vs baseline: 1.0733x; 1.0733x over previous
#include <cuda_runtime.h>
#include <cuda_bf16.h>
#include <math.h>
#include <stdint.h>

#define Bc   2
#define Sc   2048
#define HIDc 1024
#define NHc  16
#define HDc  64
#define BSc  (Bc * Sc)
#define BHc  (Bc * NHc)

#define LDg 24    // smem bf16 row stride for BK=16 proj tiles
#define LDs 72    // smem bf16 row stride (64 data + 8 pad), conflict-free
#define LDsim 136 // smem float row stride for sim tile

// Scratch (device globals — no allocation allowed)
__device__ __nv_bfloat16 g_Qh[(size_t)BHc * Sc * HDc];  // [bh][s][d] hi
__device__ __nv_bfloat16 g_Ql[(size_t)BHc * Sc * HDc];  // [bh][s][d] lo
__device__ __nv_bfloat16 g_Kh[(size_t)BHc * Sc * HDc];
__device__ __nv_bfloat16 g_Kl[(size_t)BHc * Sc * HDc];
__device__ __nv_bfloat16 g_Vh[(size_t)BHc * Sc * HDc];  // [bh][d][s] hi
__device__ __nv_bfloat16 g_Vl[(size_t)BHc * Sc * HDc];  // [bh][d][s] lo
__device__ float g_O[(size_t)Bc  * Sc * HIDc];          // [b][s][hid]
__device__ float g_part[(size_t)BHc * Sc * 16];
__device__ float g_inv [(size_t)BHc * Sc];

// ---------------------------------------------------------------------------
// helpers
// ---------------------------------------------------------------------------
__device__ __forceinline__ uint32_t ld32bf(const __nv_bfloat16* p) {
    return *reinterpret_cast<const uint32_t*>(p);
}
__device__ __forceinline__ uint32_t pack_bf16x2(float x0, float x1) {
    uint32_t r;
    asm("cvt.rn.bf16x2.f32 %0, %1, %2;" : "=r"(r) : "f"(x1), "f"(x0));
    return r;
}
__device__ __forceinline__ void mma_bf16(float c[4], const uint32_t a[4], const uint32_t b[2]) {
    asm volatile(
        "mma.sync.aligned.m16n8k16.row.col.f32.bf16.bf16.f32 "
        "{%0,%1,%2,%3},{%4,%5,%6,%7},{%8,%9},{%0,%1,%2,%3};"
        : "+f"(c[0]), "+f"(c[1]), "+f"(c[2]), "+f"(c[3])
        : "r"(a[0]), "r"(a[1]), "r"(a[2]), "r"(a[3]), "r"(b[0]), "r"(b[1]));
}
__device__ __forceinline__ void cp_async16(void* smem_ptr, const void* gptr) {
    uint32_t s = (uint32_t)__cvta_generic_to_shared(smem_ptr);
    asm volatile("cp.async.cg.shared.global [%0], [%1], 16;" :: "r"(s), "l"(gptr));
}
#define CP_COMMIT() asm volatile("cp.async.commit_group;" ::: "memory")
#define CP_WAIT(n)  asm volatile("cp.async.wait_group %0;" :: "n"(n) : "memory")

// fp32 -> bf16 hi (exact top-16 bits) + bf16 lo (residual)
__device__ __forceinline__ void cvt_store8(const float v[8],
                                           __nv_bfloat16* hi, __nv_bfloat16* lo) {
    uint32_t h[4], l[4];
    #pragma unroll
    for (int i = 0; i < 4; ++i) {
        uint32_t u0 = __float_as_uint(v[2*i]);
        uint32_t u1 = __float_as_uint(v[2*i+1]);
        h[i] = (u0 >> 16) | (u1 & 0xFFFF0000u);
        float l0 = v[2*i]   - __uint_as_float(u0 & 0xFFFF0000u);
        float l1 = v[2*i+1] - __uint_as_float(u1 & 0xFFFF0000u);
        l[i] = pack_bf16x2(l0, l1);
    }
    *reinterpret_cast<uint4*>(hi) = make_uint4(h[0], h[1], h[2], h[3]);
    *reinterpret_cast<uint4*>(lo) = make_uint4(l[0], l[1], l[2], l[3]);
}
__device__ __forceinline__ void cvt_store4(const float v[4],
                                           __nv_bfloat16* hi, __nv_bfloat16* lo) {
    uint32_t h[2], l[2];
    #pragma unroll
    for (int i = 0; i < 2; ++i) {
        uint32_t u0 = __float_as_uint(v[2*i]);
        uint32_t u1 = __float_as_uint(v[2*i+1]);
        h[i] = (u0 >> 16) | (u1 & 0xFFFF0000u);
        float l0 = v[2*i]   - __uint_as_float(u0 & 0xFFFF0000u);
        float l1 = v[2*i+1] - __uint_as_float(u1 & 0xFFFF0000u);
        l[i] = pack_bf16x2(l0, l1);
    }
    *reinterpret_cast<uint2*>(hi) = make_uint2(h[0], h[1]);
    *reinterpret_cast<uint2*>(lo) = make_uint2(l[0], l[1]);
}
__device__ __forceinline__ void cvt_store2(const float v[2],
                                           __nv_bfloat16* hi, __nv_bfloat16* lo) {
    uint32_t u0 = __float_as_uint(v[0]);
    uint32_t u1 = __float_as_uint(v[1]);
    uint32_t h = (u0 >> 16) | (u1 & 0xFFFF0000u);
    float l0 = v[0] - __uint_as_float(u0 & 0xFFFF0000u);
    float l1 = v[1] - __uint_as_float(u1 & 0xFFFF0000u);
    *reinterpret_cast<uint32_t*>(hi) = h;
    *reinterpret_cast<uint32_t*>(lo) = pack_bf16x2(l0, l1);
}
__device__ __forceinline__ void cvt1(float v, __nv_bfloat16* hi, __nv_bfloat16* lo) {
    uint32_t u = __float_as_uint(v);
    *reinterpret_cast<uint16_t*>(hi) = (uint16_t)(u >> 16);
    *lo = __float2bfloat16(v - __uint_as_float(u & 0xFFFF0000u));
}
__device__ __forceinline__ void gload4(const float* p, float r[4]) {
    float4 x = *reinterpret_cast<const float4*>(p);
    r[0]=x.x; r[1]=x.y; r[2]=x.z; r[3]=x.w;
}

// One BK=16 MMA step for a warp tile (MI x NJ m16n8 tiles), bf16x3 split.
template<int MI, int NJ, int LDm>
__device__ __forceinline__ void mma_tile(
    const __nv_bfloat16* Ah, const __nv_bfloat16* Al,
    const __nv_bfloat16* Bh, const __nv_bfloat16* Bl,
    int aRow0, int bCol0, int g, int t,
    float (&c)[MI][NJ][4])
{
    uint32_t ah[MI][4], al[MI][4], bh[NJ][2], bl[NJ][2];
    #pragma unroll
    for (int mi = 0; mi < MI; ++mi) {
        int r = aRow0 + mi * 16 + g;
        const __nv_bfloat16* p0 = Ah + r * LDm + 2 * t;
        const __nv_bfloat16* p1 = p0 + 8 * LDm;
        ah[mi][0] = ld32bf(p0);     ah[mi][1] = ld32bf(p1);
        ah[mi][2] = ld32bf(p0 + 8); ah[mi][3] = ld32bf(p1 + 8);
        const __nv_bfloat16* q0 = Al + r * LDm + 2 * t;
        const __nv_bfloat16* q1 = q0 + 8 * LDm;
        al[mi][0] = ld32bf(q0);     al[mi][1] = ld32bf(q1);
        al[mi][2] = ld32bf(q0 + 8); al[mi][3] = ld32bf(q1 + 8);
    }
    #pragma unroll
    for (int nj = 0; nj < NJ; ++nj) {
        int n = bCol0 + nj * 8 + g;
        const __nv_bfloat16* p = Bh + n * LDm + 2 * t;
        bh[nj][0] = ld32bf(p); bh[nj][1] = ld32bf(p + 8);
        const __nv_bfloat16* q = Bl + n * LDm + 2 * t;
        bl[nj][0] = ld32bf(q); bl[nj][1] = ld32bf(q + 8);
    }
    #pragma unroll
    for (int mi = 0; mi < MI; ++mi)
        #pragma unroll
        for (int nj = 0; nj < NJ; ++nj) {
            mma_bf16(c[mi][nj], ah[mi], bh[nj]);
            mma_bf16(c[mi][nj], ah[mi], bl[nj]);
            mma_bf16(c[mi][nj], al[mi], bh[nj]);
        }
}

// ---------------------------------------------------------------------------
// GEMM core: 128x128 tile, 512 thr, warp grid 4x4 (warp tile 32x32), dbl buf.
// mode 0: plain fp32 C[M,N]; mode 1: hi/lo bf16 -> [bh][s][d]; mode 2: hi/lo -> [bh][d][s]
// ---------------------------------------------------------------------------
__device__ __forceinline__ void gemm_body(
    const float* __restrict__ A, const float* __restrict__ W,
    const float* __restrict__ bias, float* __restrict__ C,
    __nv_bfloat16* __restrict__ Ch, __nv_bfloat16* __restrict__ Cl,
    int N, int K, int mode,
    __nv_bfloat16 (*sA)[2][128 * LDg], __nv_bfloat16 (*sB)[2][128 * LDg])
{
    const int tid = threadIdx.x;
    const int wid = tid >> 5, lane = tid & 31;
    const int wm = wid >> 2, wn = wid & 3;
    const int g = lane >> 2, t = lane & 3;
    const int m0 = blockIdx.y * 128, n0 = blockIdx.x * 128;

    const int lrow = tid >> 2, lcol = (tid & 3) * 4;
    const float* Ap = A + (size_t)(m0 + lrow) * K + lcol;
    const float* Bp = W + (size_t)(n0 + lrow) * K + lcol;

    float c[2][4][4];
    #pragma unroll
    for (int i = 0; i < 2; ++i)
        #pragma unroll
        for (int j = 0; j < 4; ++j)
            #pragma unroll
            for (int k = 0; k < 4; ++k) c[i][j][k] = 0.f;

    float ra[4], rb[4];
    const int KT = K >> 4;

    gload4(Ap, ra);
    gload4(Bp, rb);
    cvt_store4(ra, &sA[0][0][lrow*LDg + lcol], &sA[0][1][lrow*LDg + lcol]);
    cvt_store4(rb, &sB[0][0][lrow*LDg + lcol], &sB[0][1][lrow*LDg + lcol]);
    __syncthreads();

    for (int kt = 0; kt < KT; ++kt) {
        int cur = kt & 1;
        if (kt + 1 < KT) {
            gload4(Ap + (kt + 1) * 16, ra);
            gload4(Bp + (kt + 1) * 16, rb);
        }
        mma_tile<2,4,LDg>(sA[cur][0], sA[cur][1], sB[cur][0], sB[cur][1],
                          wm * 32, wn * 32, g, t, c);
        if (kt + 1 < KT) {
            int nxt = cur ^ 1;
            cvt_store4(ra, &sA[nxt][0][lrow*LDg + lcol], &sA[nxt][1][lrow*LDg + lcol]);
            cvt_store4(rb, &sB[nxt][0][lrow*LDg + lcol], &sB[nxt][1][lrow*LDg + lcol]);
        }
        __syncthreads();
    }

    #pragma unroll
    for (int nj = 0; nj < 4; ++nj) {
        int n = n0 + wn * 32 + nj * 8 + 2 * t;
        float b0 = bias[n], b1 = bias[n + 1];
        #pragma unroll
        for (int mi = 0; mi < 2; ++mi) {
            #pragma unroll
            for (int half = 0; half < 2; ++half) {
                int rr = m0 + wm * 32 + mi * 16 + half * 8 + g;
                float v0 = c[mi][nj][2*half]     + b0;
                float v1 = c[mi][nj][2*half + 1] + b1;
                if (mode == 0) {
                    *reinterpret_cast<float2*>(&C[(size_t)rr * N + n]) = make_float2(v0, v1);
                } else {
                    int b = rr / Sc, s = rr % Sc;
                    int h = n / HDc, d = n % HDc;
                    if (mode == 1) {
                        size_t idx = (((size_t)(b * NHc + h)) * Sc + s) * HDc + d;
                        float vv[2] = {v0, v1};
                        cvt_store2(vv, &Ch[idx], &Cl[idx]);
                    } else {
                        size_t base = ((size_t)(b * NHc + h)) * HDc;
                        cvt1(v0, &Ch[(base + d)     * Sc + s], &Cl[(base + d)     * Sc + s]);
                        cvt1(v1, &Ch[(base + d + 1) * Sc + s], &Cl[(base + d + 1) * Sc + s]);
                    }
                }
            }
        }
    }
}

// Fused Q/K/V projections: blockIdx.z selects the GEMM.
__global__ __launch_bounds__(512, 1) void qkv_kernel(
    const float* __restrict__ query, const float* __restrict__ key,
    const float* __restrict__ value,
    const float* __restrict__ Wq, const float* __restrict__ bq,
    const float* __restrict__ Wk, const float* __restrict__ bk,
    const float* __restrict__ Wv, const float* __restrict__ bv,
    __nv_bfloat16* Qh, __nv_bfloat16* Ql,
    __nv_bfloat16* Kh, __nv_bfloat16* Kl,
    __nv_bfloat16* Vh, __nv_bfloat16* Vl)
{
    __shared__ __nv_bfloat16 sA[2][2][128 * LDg];
    __shared__ __nv_bfloat16 sB[2][2][128 * LDg];
    const float *A, *W, *bias; __nv_bfloat16 *Ch, *Cl; int mode;
    if (blockIdx.z == 0)      { A = query; W = Wq; bias = bq; Ch = Qh; Cl = Ql; mode = 1; }
    else if (blockIdx.z == 1) { A = key;   W = Wk; bias = bk; Ch = Kh; Cl = Kl; mode = 1; }
    else                      { A = value; W = Wv; bias = bv; Ch = Vh; Cl = Vl; mode = 2; }
    gemm_body(A, W, bias, nullptr, Ch, Cl, HIDc, HIDc, mode, sA, sB);
}

// Output projection (plain fp32)
__global__ __launch_bounds__(512, 1) void oproj_kernel(
    const float* __restrict__ A, const float* __restrict__ W,
    const float* __restrict__ bias, float* __restrict__ C)
{
    __shared__ __nv_bfloat16 sA[2][2][128 * LDg];
    __shared__ __nv_bfloat16 sB[2][2][128 * LDg];
    gemm_body(A, W, bias, C, nullptr, nullptr, HIDc, HIDc, 0, sA, sB);
}

// ---------------------------------------------------------------------------
// Scores: e = exp(QK/8 + beta*sim, masked) -> weights region + row partials.
// Q/K staged via cp.async from preconverted bf16 hi/lo; sim prefetched async.
// ---------------------------------------------------------------------------
__global__ __launch_bounds__(512, 1) void scores_kernel(
    const float* __restrict__ sim, const int* __restrict__ mask,
    const float* __restrict__ beta_p, float* __restrict__ Wt)
{
    extern __shared__ __nv_bfloat16 dsm[];
    __nv_bfloat16* sAh = dsm;
    __nv_bfloat16* sAl = sAh + 128 * LDs;
    __nv_bfloat16* sBh = sAl + 128 * LDs;
    __nv_bfloat16* sBl = sBh + 128 * LDs;
    float* ssim = reinterpret_cast<float*>(sBl + 128 * LDs);  // [128][LDsim]
    __shared__ float spart[128][4];

    const int tid = threadIdx.x;
    const int wid = tid >> 5, lane = tid & 31;
    const int wm = wid >> 2, wn = wid & 3;
    const int g = lane >> 2, t = lane & 3;
    const int bh = blockIdx.z, b = bh >> 4;
    const int m0 = blockIdx.y * 128, n0 = blockIdx.x * 128;

    // --- group 1: Q/K hi/lo tiles via cp.async ---
    {
        const int r = tid >> 2, c0 = (tid & 3) * 16;
        const size_t qoff = (size_t)bh * Sc * HDc + (size_t)(m0 + r) * HDc + c0;
        const size_t koff = (size_t)bh * Sc * HDc + (size_t)(n0 + r) * HDc + c0;
        cp_async16(&sAh[r*LDs + c0],     g_Qh + qoff);
        cp_async16(&sAh[r*LDs + c0 + 8], g_Qh + qoff + 8);
        cp_async16(&sAl[r*LDs + c0],     g_Ql + qoff);
        cp_async16(&sAl[r*LDs + c0 + 8], g_Ql + qoff + 8);
        cp_async16(&sBh[r*LDs + c0],     g_Kh + koff);
        cp_async16(&sBh[r*LDs + c0 + 8], g_Kh + koff + 8);
        cp_async16(&sBl[r*LDs + c0],     g_Kl + koff);
        cp_async16(&sBl[r*LDs + c0 + 8], g_Kl + koff + 8);
        CP_COMMIT();
    }
    // --- group 2: sim tile ---
    {
        const int r = tid >> 2, c0 = (tid & 3) * 32;
        const float* gsrc = sim + ((size_t)b * Sc + m0 + r) * Sc + n0 + c0;
        float* sdst = ssim + r * LDsim + c0;
        #pragma unroll
        for (int i = 0; i < 8; ++i)
            cp_async16(sdst + i * 4, gsrc + i * 4);
        CP_COMMIT();
    }

    CP_WAIT(1);          // Q/K ready
    __syncthreads();

    float c[2][4][4];
    #pragma unroll
    for (int i = 0; i < 2; ++i)
        #pragma unroll
        for (int j = 0; j < 4; ++j)
            #pragma unroll
            for (int k = 0; k < 4; ++k) c[i][j][k] = 0.f;

    #pragma unroll
    for (int kt = 0; kt < HDc / 16; ++kt) {
        mma_tile<2,4,LDs>(sAh + kt*16, sAl + kt*16, sBh + kt*16, sBl + kt*16,
                          wm * 32, wn * 32, g, t, c);
    }

    CP_WAIT(0);          // sim ready
    __syncthreads();

    const float beta = *beta_p;
    int2 mk[4];
    #pragma unroll
    for (int nj = 0; nj < 4; ++nj)
        mk[nj] = *reinterpret_cast<const int2*>(
            &mask[b * Sc + n0 + wn * 32 + nj * 8 + 2 * t]);

    float rsum[2][2];
    rsum[0][0] = rsum[0][1] = rsum[1][0] = rsum[1][1] = 0.f;

    #pragma unroll
    for (int mi = 0; mi < 2; ++mi) {
        #pragma unroll
        for (int half = 0; half < 2; ++half) {
            int rloc = wm * 32 + mi * 16 + half * 8 + g;
            int qq = m0 + rloc;
            #pragma unroll
            for (int nj = 0; nj < 4; ++nj) {
                int cloc = wn * 32 + nj * 8 + 2 * t;
                float2 sv = *reinterpret_cast<const float2*>(&ssim[rloc * LDsim + cloc]);
                float s0 = c[mi][nj][2*half]     * 0.125f + beta * sv.x;
                float s1 = c[mi][nj][2*half + 1] * 0.125f + beta * sv.y;
                if (mk[nj].x == 0) s0 = -1e30f;
                if (mk[nj].y == 0) s1 = -1e30f;
                float e0 = __expf(s0), e1 = __expf(s1);
                __stcs(reinterpret_cast<float2*>(
                    &Wt[((size_t)bh * Sc + qq) * Sc + n0 + cloc]), make_float2(e0, e1));
                rsum[mi][half] += e0 + e1;
            }
        }
    }
    #pragma unroll
    for (int mi = 0; mi < 2; ++mi)
        #pragma unroll
        for (int half = 0; half < 2; ++half) {
            float v = rsum[mi][half];
            v += __shfl_xor_sync(0xffffffffu, v, 1);
            v += __shfl_xor_sync(0xffffffffu, v, 2);
            if (t == 0) spart[wm * 32 + mi * 16 + half * 8 + g][wn] = v;
        }
    __syncthreads();
    if (tid < 128) {
        float s = spart[tid][0] + spart[tid][1] + spart[tid][2] + spart[tid][3];
        g_part[((size_t)bh * Sc + m0 + tid) * 16 + blockIdx.x] = s;
    }
}

// ---------------------------------------------------------------------------
// inv rowsum
// ---------------------------------------------------------------------------
__global__ __launch_bounds__(256) void inv_kernel()
{
    int i = blockIdx.x * 256 + threadIdx.x;
    const float4* p = reinterpret_cast<const float4*>(g_part + (size_t)i * 16);
    float4 a = p[0], bb = p[1], cc = p[2], d = p[3];
    float s = ((a.x + a.y) + (a.z + a.w)) + ((bb.x + bb.y) + (bb.z + bb.w))
            + ((cc.x + cc.y) + (cc.z + cc.w)) + ((d.x + d.y) + (d.z + d.w));
    g_inv[i] = 1.0f / s;
}

// ---------------------------------------------------------------------------
// AV: normalize e -> p in-place (final attention_weights), O = P @ V^T.
// 128x64 tile, 512 threads, warp grid 4m x 4n (warp tile 32x16).
// BK=64 double-buffered: 4 independent e-loads/thread/iter (MLP=4), V via
// cp.async (preconverted bf16), 32 iterations. Dynamic smem 108 KB.
// ---------------------------------------------------------------------------
__global__ __launch_bounds__(512, 1) void av_kernel(float* __restrict__ Wt)
{
    extern __shared__ __nv_bfloat16 dsm[];
    __nv_bfloat16* sAh[2] = { dsm,            dsm + 2 * 128 * LDs };
    __nv_bfloat16* sAl[2] = { dsm + 128*LDs,  dsm + 3 * 128 * LDs };
    __nv_bfloat16* bbase  = dsm + 4 * 128 * LDs;
    __nv_bfloat16* sBh[2] = { bbase,          bbase + 2 * 64 * LDs };
    __nv_bfloat16* sBl[2] = { bbase + 64*LDs, bbase + 3 * 64 * LDs };

    const int tid = threadIdx.x;
    const int wid = tid >> 5, lane = tid & 31;
    const int wm = wid >> 2, wn = wid & 3;      // warp tile 32m x 16d
    const int g = lane >> 2, t = lane & 3;
    const int bh = blockIdx.z, b = bh >> 4, h = bh & 15;
    const int m0 = blockIdx.x * 128;

    // A (e/p) mapping: row = tid>>2 (0..127), cols (tid&3)*16 .. +15
    const int rowA = tid >> 2, c0A = (tid & 3) * 16;
    float* ApE = Wt + (size_t)bh * Sc * Sc + (size_t)(m0 + rowA) * Sc;
    const float inv = g_inv[(size_t)bh * Sc + m0 + rowA];

    // B (V) mapping: d = tid>>3 (0..63), col chunk (tid&7)*8
    const int dB = tid >> 3, cB = (tid & 7) * 8;
    const size_t vbase = (size_t)bh * HDc * Sc + (size_t)dB * Sc + cB;

    float c[2][2][4];
    #pragma unroll
    for (int i = 0; i < 2; ++i)
        #pragma unroll
        for (int j = 0; j < 2; ++j)
            #pragma unroll
            for (int k = 0; k < 4; ++k) c[i][j][k] = 0.f;

    const int KT = Sc / 64;  // 32
    float ra[16];

    // helper lambdas (inlined by compiler)
    auto loadA = [&](int ktn) {
        float* p = ApE + ktn * 64 + c0A;
        float4 x0 = __ldcs(reinterpret_cast<const float4*>(p));
        float4 x1 = __ldcs(reinterpret_cast<const float4*>(p + 4));
        float4 x2 = __ldcs(reinterpret_cast<const float4*>(p + 8));
        float4 x3 = __ldcs(reinterpret_cast<const float4*>(p + 12));
        x0.x*=inv; x0.y*=inv; x0.z*=inv; x0.w*=inv;
        x1.x*=inv; x1.y*=inv; x1.z*=inv; x1.w*=inv;
        x2.x*=inv; x2.y*=inv; x2.z*=inv; x2.w*=inv;
        x3.x*=inv; x3.y*=inv; x3.z*=inv; x3.w*=inv;
        __stcs(reinterpret_cast<float4*>(p),      x0);
        __stcs(reinterpret_cast<float4*>(p + 4),  x1);
        __stcs(reinterpret_cast<float4*>(p + 8),  x2);
        __stcs(reinterpret_cast<float4*>(p + 12), x3);
        ra[0]=x0.x; ra[1]=x0.y; ra[2]=x0.z;  ra[3]=x0.w;
        ra[4]=x1.x; ra[5]=x1.y; ra[6]=x1.z;  ra[7]=x1.w;
        ra[8]=x2.x; ra[9]=x2.y; ra[10]=x2.z; ra[11]=x2.w;
        ra[12]=x3.x;ra[13]=x3.y;ra[14]=x3.z; ra[15]=x3.w;
    };
    auto storeA = [&](int buf) {
        cvt_store8(ra,     &sAh[buf][rowA*LDs + c0A],     &sAl[buf][rowA*LDs + c0A]);
        cvt_store8(ra + 8, &sAh[buf][rowA*LDs + c0A + 8], &sAl[buf][rowA*LDs + c0A + 8]);
    };
    auto loadB = [&](int ktn, int buf) {
        cp_async16(&sBh[buf][dB*LDs + cB], g_Vh + vbase + ktn * 64);
        cp_async16(&sBl[buf][dB*LDs + cB], g_Vl + vbase + ktn * 64);
        CP_COMMIT();
    };

    // prologue: fill buf 0
    loadB(0, 0);
    loadA(0);
    storeA(0);
    CP_WAIT(0);
    __syncthreads();

    for (int kt = 0; kt < KT; ++kt) {
        int cur = kt & 1;
        if (kt + 1 < KT) {
            loadB(kt + 1, cur ^ 1);
            loadA(kt + 1);
        }
        #pragma unroll
        for (int ks = 0; ks < 4; ++ks) {
            mma_tile<2,2,LDs>(sAh[cur] + ks*16, sAl[cur] + ks*16,
                              sBh[cur] + ks*16, sBl[cur] + ks*16,
                              wm * 32, wn * 16, g, t, c);
        }
        if (kt + 1 < KT) {
            storeA(cur ^ 1);
            CP_WAIT(0);
        }
        __syncthreads();
    }

    #pragma unroll
    for (int mi = 0; mi < 2; ++mi)
        #pragma unroll
        for (int nj = 0; nj < 2; ++nj)
            #pragma unroll
            for (int half = 0; half < 2; ++half) {
                int q = m0 + wm * 32 + mi * 16 + half * 8 + g;
                int d = wn * 16 + nj * 8 + 2 * t;
                float2 vv = make_float2(c[mi][nj][2*half], c[mi][nj][2*half + 1]);
                *reinterpret_cast<float2*>(
                    &g_O[((size_t)(b * Sc) + q) * HIDc + h * HDc + d]) = vv;
            }
}

// ---------------------------------------------------------------------------
extern "C" void kernel_launch(void* const* d_in, const int* in_sizes, int n_in,
                              void* d_out, int out_size)
{
    (void)in_sizes; (void)n_in; (void)out_size;
    const float* query = (const float*)d_in[0];
    const float* key   = (const float*)d_in[1];
    const float* value = (const float*)d_in[2];
    const int*   amask = (const int*)  d_in[3];
    const float* sim   = (const float*)d_in[4];
    const float* Wq    = (const float*)d_in[5];
    const float* bq    = (const float*)d_in[6];
    const float* Wk    = (const float*)d_in[7];
    const float* bk    = (const float*)d_in[8];
    const float* Wv    = (const float*)d_in[9];
    const float* bv    = (const float*)d_in[10];
    const float* Wo    = (const float*)d_in[11];
    const float* bo    = (const float*)d_in[12];
    const float* beta  = (const float*)d_in[13];

    float* out     = (float*)d_out;                      // [B,S,HID]
    float* weights = out + (size_t)Bc * Sc * HIDc;       // [B,NH,S,S]

    const int SCORES_SMEM = 4 * 128 * LDs * 2 + 128 * LDsim * 4;      // 143360
    const int AV_SMEM     = (4 * 128 * LDs + 4 * 64 * LDs) * 2;       // 110592

    static __nv_bfloat16 *Qh=nullptr,*Ql=nullptr,*Kh=nullptr,*Kl=nullptr,*Vh=nullptr,*Vl=nullptr;
    static float *Op = nullptr;
    if (!Qh) {
        cudaGetSymbolAddress((void**)&Qh, g_Qh);
        cudaGetSymbolAddress((void**)&Ql, g_Ql);
        cudaGetSymbolAddress((void**)&Kh, g_Kh);
        cudaGetSymbolAddress((void**)&Kl, g_Kl);
        cudaGetSymbolAddress((void**)&Vh, g_Vh);
        cudaGetSymbolAddress((void**)&Vl, g_Vl);
        cudaGetSymbolAddress((void**)&Op, g_O);
        cudaFuncSetAttribute(scores_kernel,
            cudaFuncAttributeMaxDynamicSharedMemorySize, SCORES_SMEM);
        cudaFuncSetAttribute(av_kernel,
            cudaFuncAttributeMaxDynamicSharedMemorySize, AV_SMEM);
    }

    dim3 blk(512);

    dim3 gqkv(HIDc / 128, BSc / 128, 3);   // 768 CTAs
    qkv_kernel<<<gqkv, blk>>>(query, key, value, Wq, bq, Wk, bk, Wv, bv,
                              Qh, Ql, Kh, Kl, Vh, Vl);

    dim3 gsc(Sc / 128, Sc / 128, BHc);     // (16, 16, 32)
    scores_kernel<<<gsc, blk, SCORES_SMEM>>>(sim, amask, beta, weights);

    inv_kernel<<<(BHc * Sc) / 256, 256>>>();

    dim3 gav(Sc / 128, 1, BHc);            // 512 CTAs
    av_kernel<<<gav, blk, AV_SMEM>>>(weights);

    dim3 gop(HIDc / 128, BSc / 128);
    oproj_kernel<<<gop, blk>>>(Op, Wo, bo, out);
}